// round 11
// baseline (speedup 1.0000x reference)
#include <cuda_runtime.h>
#include <cstdint>

#define NJ 50
#define EDIM 192
#define NJP 56
#define ETSTRIDE 56       // Et [k][j] stride (floats); j>=50 zero, see=+inf
#define NWARP 7
#define NTHREADS 224
#define RPT 5
#define ROWS_PER_WARP 40
#define ROWS_PER_BLOCK 280
#define XSTRIDE4 9        // xs row stride in float4 (8 + 1 pad)

// dynamic smem byte offsets
#define OFF_ET   0
#define OFF_XS   43008                      // 192*56*4
#define OFF_SEE  (OFF_XS + 40320)           // 280*9*16
#define OFF_BJ   (OFF_SEE + 224)
#define OFF_WRED (OFF_BJ + 1120)
#define SMEM_TOTAL (OFF_WRED + 32)          // 84704 B -> 2 CTAs/SM

__device__ double g_loss_sum;     // zero-init at module load
__device__ unsigned int g_done;

static __device__ __forceinline__ unsigned long long pack2s(float v) {
    unsigned long long r;
    asm("mov.b64 %0, {%1, %1};" : "=l"(r) : "f"(v));
    return r;
}
static __device__ __forceinline__ void unpack2(unsigned long long v, float& lo, float& hi) {
    asm("mov.b64 {%0, %1}, %2;" : "=f"(lo), "=f"(hi) : "l"(v));
}
static __device__ __forceinline__ unsigned long long fma2(unsigned long long a,
                                                          unsigned long long b,
                                                          unsigned long long c) {
    unsigned long long d;
    asm("fma.rn.f32x2 %0, %1, %2, %3;" : "=l"(d) : "l"(a), "l"(b), "l"(c));
    return d;
}

// lane = (g<<2)|js : js in [0,4) code split (j = 14*js+jj), g in [0,8).
// Thread rows: warpbase + g + 8*i, i=0..4 (5 rows/thread, 40 rows/warp).
// acc f32x2 = CODE PAIR, e = raw LDS.64; x staged coalesced through smem.
__global__ void __launch_bounds__(NTHREADS, 2) vq_kernel(
        const float* __restrict__ x, const float* __restrict__ e,
        float* __restrict__ out, int n) {
    extern __shared__ __align__(16) char smem[];
    float*  Et   = (float*)(smem + OFF_ET);
    float4* xs4  = (float4*)(smem + OFF_XS);
    float*  see  = (float*)(smem + OFF_SEE);
    int*    bjsh = (int*)(smem + OFF_BJ);
    float*  wred = (float*)(smem + OFF_WRED);

    const int tid = threadIdx.x;
    const int wid = tid >> 5;
    const int lane = tid & 31;
    const int js = lane & 3;
    const int g = lane >> 2;

    // ---- init: zero Et, fill [k][j] transpose, see (+inf pads) ----
    for (int i = tid; i < EDIM * ETSTRIDE; i += NTHREADS) Et[i] = 0.f;
    __syncthreads();
    for (int i = tid; i < NJ * EDIM; i += NTHREADS) {
        int j = i / EDIM, k = i - j * EDIM;        // e[j][k] coalesced
        Et[k * ETSTRIDE + j] = e[i];
    }
    if (tid < NJP) {
        float s = 3.402823466e38f;
        if (tid < NJ) {
            s = 0.f;
            const float* ej = e + (size_t)tid * EDIM;
            #pragma unroll 4
            for (int k = 0; k < EDIM; ++k) { float v = __ldg(ej + k); s = fmaf(v, v, s); }
        }
        see[tid] = s;
    }
    __syncthreads();

    const int tile_base = blockIdx.x * ROWS_PER_BLOCK;
    const int warpbase = wid * ROWS_PER_WARP;

    unsigned long long acc[RPT][7];
    float s0[RPT], s1[RPT];                        // ||x||^2: x,z -> s0 ; y,w -> s1
    #pragma unroll
    for (int i = 0; i < RPT; ++i) {
        s0[i] = 0.f; s1[i] = 0.f;
        #pragma unroll
        for (int p = 0; p < 7; ++p) acc[i][p] = 0ULL;
    }

    const float4* x4 = reinterpret_cast<const float4*>(x);
    const int ebase = 14 * js;

    // ---- main loop: 6 chunks of 8 float4-kq, x staged coalesced in smem ----
    #pragma unroll 1
    for (int ch = 0; ch < 6; ++ch) {
        const int kqb = ch * 8;
        __syncthreads();                           // xs free from previous chunk
        #pragma unroll
        for (int i = 0; i < 10; ++i) {             // 2240 float4 = 280 rows x 8
            const int idx = tid + i * NTHREADS;
            const int row = idx >> 3, kql = idx & 7;
            int gr = tile_base + row; if (gr >= n) gr = n - 1;
            xs4[row * XSTRIDE4 + kql] = __ldg(x4 + (size_t)gr * 48 + kqb + kql);
        }
        __syncthreads();

        #pragma unroll 1
        for (int kql = 0; kql < 8; ++kql) {
            const int kq = kqb + kql;
            float4 xv[RPT];
            #pragma unroll
            for (int i = 0; i < RPT; ++i)
                xv[i] = xs4[(warpbase + g + 8 * i) * XSTRIDE4 + kql];

            #pragma unroll
            for (int c = 0; c < 4; ++c) {
                const int k = kq * 4 + c;
                const unsigned long long* ep =
                    reinterpret_cast<const unsigned long long*>(&Et[k * ETSTRIDE + ebase]);
                float a0, a1, a2, a3, a4;
                if (c == 0)      { a0=xv[0].x; a1=xv[1].x; a2=xv[2].x; a3=xv[3].x; a4=xv[4].x; }
                else if (c == 1) { a0=xv[0].y; a1=xv[1].y; a2=xv[2].y; a3=xv[3].y; a4=xv[4].y; }
                else if (c == 2) { a0=xv[0].z; a1=xv[1].z; a2=xv[2].z; a3=xv[3].z; a4=xv[4].z; }
                else             { a0=xv[0].w; a1=xv[1].w; a2=xv[2].w; a3=xv[3].w; a4=xv[4].w; }
                if ((c & 1) == 0) {
                    s0[0] = fmaf(a0, a0, s0[0]); s0[1] = fmaf(a1, a1, s0[1]);
                    s0[2] = fmaf(a2, a2, s0[2]); s0[3] = fmaf(a3, a3, s0[3]);
                    s0[4] = fmaf(a4, a4, s0[4]);
                } else {
                    s1[0] = fmaf(a0, a0, s1[0]); s1[1] = fmaf(a1, a1, s1[1]);
                    s1[2] = fmaf(a2, a2, s1[2]); s1[3] = fmaf(a3, a3, s1[3]);
                    s1[4] = fmaf(a4, a4, s1[4]);
                }
                const unsigned long long xp0 = pack2s(a0), xp1 = pack2s(a1);
                const unsigned long long xp2 = pack2s(a2), xp3 = pack2s(a3);
                const unsigned long long xp4 = pack2s(a4);
                #pragma unroll
                for (int p = 0; p < 7; ++p) {
                    const unsigned long long ev = ep[p];   // LDS.64: codes (2p,2p+1)
                    acc[0][p] = fma2(xp0, ev, acc[0][p]);
                    acc[1][p] = fma2(xp1, ev, acc[1][p]);
                    acc[2][p] = fma2(xp2, ev, acc[2][p]);
                    acc[3][p] = fma2(xp3, ev, acc[3][p]);
                    acc[4][p] = fma2(xp4, ev, acc[4][p]);
                }
            }
        }
    }

    // ---- per-thread argmin (exact R2 compare), combine over 4 js-lanes ----
    #pragma unroll
    for (int i = 0; i < RPT; ++i) {
        const float sxx = s0[i] + s1[i];
        float v = 3.402823466e38f;
        int jx = 0;
        #pragma unroll
        for (int p = 0; p < 7; ++p) {
            float dlo, dhi;
            unpack2(acc[i][p], dlo, dhi);
            const int j = ebase + 2 * p;
            float mlo = __fsub_rn(__fadd_rn(sxx, see[j]),     2.0f * dlo);
            float mhi = __fsub_rn(__fadd_rn(sxx, see[j + 1]), 2.0f * dhi);
            if (mlo < v) { v = mlo; jx = j; }
            if (mhi < v) { v = mhi; jx = j + 1; }
        }
        #pragma unroll
        for (int mask = 1; mask <= 2; mask <<= 1) {
            float ov = __shfl_xor_sync(0xffffffffu, v, mask);
            int   oj = __shfl_xor_sync(0xffffffffu, jx, mask);
            if (ov < v || (ov == v && oj < jx)) { v = ov; jx = oj; }
        }
        const int grow = tile_base + warpbase + g + 8 * i;
        if (js == 0) {
            bjsh[warpbase + g + 8 * i] = jx;
            if (grow < n) out[(size_t)n * EDIM + grow] = (float)jx;
        }
    }
    __syncwarp();

    // ---- phase 2: warp-cooperative coalesced straight-through write + loss ----
    float lsum = 0.f;
    const float4* e4 = reinterpret_cast<const float4*>(e);
    float4* o4 = reinterpret_cast<float4*>(out);
    #pragma unroll 4
    for (int it = 0; it < (ROWS_PER_WARP * 48) / 32; ++it) {   // 60 iters
        const int idx = it * 32 + lane;
        const int rl = idx / 48, c4 = idx - rl * 48;
        const int grow = tile_base + warpbase + rl;
        if (grow < n) {
            const int bj = bjsh[warpbase + rl];
            const float4 xq = __ldg(x4 + (size_t)grow * 48 + c4);
            const float4 qq = __ldg(e4 + (size_t)bj * 48 + c4);
            float dx = __fsub_rn(qq.x, xq.x), dy = __fsub_rn(qq.y, xq.y);
            float dz = __fsub_rn(qq.z, xq.z), dw = __fsub_rn(qq.w, xq.w);
            lsum = fmaf(dx, dx, lsum); lsum = fmaf(dy, dy, lsum);
            lsum = fmaf(dz, dz, lsum); lsum = fmaf(dw, dw, lsum);
            float4 o;
            o.x = __fadd_rn(xq.x, dx); o.y = __fadd_rn(xq.y, dy);
            o.z = __fadd_rn(xq.z, dz); o.w = __fadd_rn(xq.w, dw);
            o4[(size_t)grow * 48 + c4] = o;
        }
    }

    // ---- loss reduction + single-kernel finalize ----
    #pragma unroll
    for (int off = 16; off > 0; off >>= 1)
        lsum += __shfl_down_sync(0xffffffffu, lsum, off);
    if (lane == 0) wred[wid] = lsum;
    __syncthreads();
    if (tid == 0) {
        float bs = 0.f;
        #pragma unroll
        for (int w = 0; w < NWARP; ++w) bs += wred[w];
        atomicAdd(&g_loss_sum, (double)bs);
        __threadfence();
        unsigned int prev = atomicAdd(&g_done, 1u);
        if (prev == gridDim.x - 1) {
            __threadfence();
            double total = atomicAdd(&g_loss_sum, 0.0);
            double mean = total / ((double)n * (double)EDIM);
            out[(size_t)n * EDIM + n]     = (float)(1.25 * mean);  // (1+BETA)*mean
            out[(size_t)n * EDIM + n + 1] = 0.0f;                  // contrastloss
            g_loss_sum = 0.0;
            g_done = 0u;
            __threadfence();
        }
    }
}

extern "C" void kernel_launch(void* const* d_in, const int* in_sizes, int n_in,
                              void* d_out, int out_size) {
    (void)n_in; (void)out_size;
    const float* x = (const float*)d_in[0];   // [N, 192] fp32
    const float* e = (const float*)d_in[1];   // [50, 192] fp32
    float* out = (float*)d_out;               // [N*192 | N | 1 | 1] fp32
    const int n = in_sizes[0] / EDIM;

    static int configured = 0;
    if (!configured) {
        cudaFuncSetAttribute(vq_kernel, cudaFuncAttributeMaxDynamicSharedMemorySize,
                             SMEM_TOTAL);
        configured = 1;
    }
    const int blocks = (n + ROWS_PER_BLOCK - 1) / ROWS_PER_BLOCK;
    vq_kernel<<<blocks, NTHREADS, SMEM_TOTAL>>>(x, e, out, n);
}

// round 12
// speedup vs baseline: 1.1249x; 1.1249x over previous
#include <cuda_runtime.h>
#include <cstdint>

#define NJ 50
#define NJP 56
#define EDIM 192
#define NTHREADS 256
#define ROWS_PER_BLOCK 128
#define QMAX 2048
#define EBS 56            // Eb row stride (u32): Eb[k][j]
#define XSW 36            // xs row stride in floats (32 + 4 pad)

// dynamic smem byte offsets
#define OFF_EB   0                       // 192*56*4 = 43008
#define OFF_XS   43008                   // 128*36*4 = 18432
#define OFF_SXX  61440                   // 128*4
#define OFF_SEE  61952                   // 56*4
#define OFF_SB   62176                   // 56*4
#define OFF_BJ   62400                   // 128*4
#define OFF_RKEY 62912                   // 128*8 (8-aligned)
#define OFF_Q    63936                   // QMAX*4
#define OFF_QC   72128                   // u32
#define OFF_OFL  72132                   // 4*u32 overflow bitmask
#define OFF_WRED 72148                   // 8*4
#define SMEM_TOTAL 72192                 // -> 2 CTAs/SM

__device__ double g_loss_sum;    // zero-init at load
__device__ unsigned int g_done;

#define CVT_TF32(u, f) asm("cvt.rna.tf32.f32 %0, %1;" : "=r"(u) : "f"(f))
#define MMA_TF32(d, a0, a1, a2, a3, b0, b1) \
    asm volatile("mma.sync.aligned.m16n8k8.row.col.f32.tf32.tf32.f32 " \
        "{%0,%1,%2,%3}, {%4,%5,%6,%7}, {%8,%9}, {%0,%1,%2,%3};" \
        : "+f"((d)[0]), "+f"((d)[1]), "+f"((d)[2]), "+f"((d)[3]) \
        : "r"(a0), "r"(a1), "r"(a2), "r"(a3), "r"(b0), "r"(b1))

// Exact m for (row x, code j): bit-identical to the R2/R5/R6/R9 passing chain.
static __device__ __forceinline__ float exact_m(const float4* xrow, const float4* e4,
                                                int j, float sxx, const float* see) {
    float dd = 0.f;
    const float4* ej = e4 + (size_t)j * 48;
    #pragma unroll 4
    for (int k0 = 0; k0 < 48; ++k0) {
        const float4 xv = __ldg(xrow + k0);
        const float4 ev = __ldg(ej + k0);
        dd = fmaf(xv.x, ev.x, dd); dd = fmaf(xv.y, ev.y, dd);
        dd = fmaf(xv.z, ev.z, dd); dd = fmaf(xv.w, ev.w, dd);
    }
    return __fsub_rn(__fadd_rn(sxx, see[j]), 2.0f * dd);
}

__global__ void __launch_bounds__(NTHREADS, 2) vq_kernel(
        const float* __restrict__ x, const float* __restrict__ e,
        float* __restrict__ out, int n) {
    extern __shared__ __align__(16) char smem[];
    uint32_t* Eb     = (uint32_t*)(smem + OFF_EB);
    float4*   xs4    = (float4*)(smem + OFF_XS);
    float*    xsf    = (float*)(smem + OFF_XS);
    float*    sxx_sh = (float*)(smem + OFF_SXX);
    float*    see    = (float*)(smem + OFF_SEE);
    float*    sB     = (float*)(smem + OFF_SB);
    int*      bjsh   = (int*)(smem + OFF_BJ);
    unsigned long long* rkey = (unsigned long long*)(smem + OFF_RKEY);
    uint32_t* queue  = (uint32_t*)(smem + OFF_Q);
    uint32_t* qcnt   = (uint32_t*)(smem + OFF_QC);
    uint32_t* ofl    = (uint32_t*)(smem + OFF_OFL);
    float*    wred   = (float*)(smem + OFF_WRED);

    const int tid = threadIdx.x;
    const int wid = tid >> 5;
    const int lane = tid & 31;
    const int gid = lane >> 2;       // 0..7
    const int tig = lane & 3;        // 0..3

    // ---- init ----
    for (int i = tid; i < EDIM * EBS; i += NTHREADS) Eb[i] = 0u;
    if (tid == 0) *qcnt = 0u;
    if (tid < 4) ofl[tid] = 0u;
    if (tid < ROWS_PER_BLOCK) rkey[tid] = 0xFFFFFFFFFFFFFFFFull;
    __syncthreads();
    for (int i = tid; i < NJ * EDIM; i += NTHREADS) {
        int j = i / EDIM, k = i - j * EDIM;
        uint32_t u; CVT_TF32(u, __ldg(e + i));
        Eb[k * EBS + j] = u;
    }
    if (tid < NJP) {
        float s = 1e38f;
        if (tid < NJ) {
            s = 0.f;
            const float* ej = e + (size_t)tid * EDIM;
            #pragma unroll 4
            for (int k = 0; k < EDIM; ++k) { float v = __ldg(ej + k); s = fmaf(v, v, s); }
        }
        see[tid] = s;
        sB[tid] = (tid < NJ) ? 2.4e-3f * sqrtf(s) : 0.f;   // 2*tf32 dot bound coeff
    }

    const int tile_base = blockIdx.x * ROWS_PER_BLOCK;
    const float4* x4 = reinterpret_cast<const float4*>(x);
    const float4* e4 = reinterpret_cast<const float4*>(e);

    float d[7][4];
    #pragma unroll
    for (int nt = 0; nt < 7; ++nt)
        #pragma unroll
        for (int q = 0; q < 4; ++q) d[nt][q] = 0.f;
    float s0 = 0.f, s1 = 0.f;        // ||x||^2 partials for row 'tid' (tid<128)

    // ---- main: 6 chunks of 32 k; stage 128 rows coalesced, MMA per warp ----
    #pragma unroll 1
    for (int ch = 0; ch < 6; ++ch) {
        __syncthreads();
        #pragma unroll
        for (int i = 0; i < 4; ++i) {                 // 1024 float4 = 128 rows x 8
            const int idx = tid + i * NTHREADS;
            const int row = idx >> 3, kql = idx & 7;
            int gr = tile_base + row; if (gr >= n) gr = n - 1;
            xs4[row * 9 + kql] = __ldg(x4 + (size_t)gr * 48 + ch * 8 + kql);
        }
        __syncthreads();
        if (tid < ROWS_PER_BLOCK) {                   // exact ||x||^2 chain (R2 order)
            #pragma unroll
            for (int q = 0; q < 8; ++q) {
                const float4 v = xs4[tid * 9 + q];
                s0 = fmaf(v.x, v.x, s0); s1 = fmaf(v.y, v.y, s1);
                s0 = fmaf(v.z, v.z, s0); s1 = fmaf(v.w, v.w, s1);
            }
        }
        const int arow = wid * 16 + gid;
        #pragma unroll
        for (int kt = 0; kt < 4; ++kt) {
            const int c = kt * 8 + tig;
            uint32_t a0, a1, a2, a3;
            CVT_TF32(a0, xsf[arow * XSW + c]);
            CVT_TF32(a1, xsf[(arow + 8) * XSW + c]);
            CVT_TF32(a2, xsf[arow * XSW + c + 4]);
            CVT_TF32(a3, xsf[(arow + 8) * XSW + c + 4]);
            const int kg = ch * 32 + kt * 8 + tig;
            const uint32_t* eb0 = Eb + (size_t)kg * EBS + gid;
            const uint32_t* eb1 = Eb + (size_t)(kg + 4) * EBS + gid;
            #pragma unroll
            for (int nt = 0; nt < 7; ++nt) {
                const uint32_t b0 = eb0[nt * 8];
                const uint32_t b1 = eb1[nt * 8];
                MMA_TF32(d[nt], a0, a1, a2, a3, b0, b1);
            }
        }
    }
    if (tid < ROWS_PER_BLOCK) sxx_sh[tid] = s0 + s1;
    __syncthreads();

    // ---- screen: rigorous candidate set from tf32 dots ----
    #pragma unroll
    for (int half = 0; half < 2; ++half) {
        const int row = wid * 16 + gid + half * 8;
        const float sxx = sxx_sh[row];
        const float sqxx = sqrtf(sxx);
        float R = 3.402823466e38f;
        #pragma unroll
        for (int nt = 0; nt < 7; ++nt)
            #pragma unroll
            for (int c2 = 0; c2 < 2; ++c2) {
                const int j = nt * 8 + 2 * tig + c2;
                const float dv = d[nt][half * 2 + c2];
                const float m = __fsub_rn(__fadd_rn(sxx, see[j]), 2.0f * dv);
                const float Bv = fmaf(sqxx, sB[j], 3e-4f);
                R = fminf(R, m + Bv);
            }
        R = fminf(R, __shfl_xor_sync(0xffffffffu, R, 1));
        R = fminf(R, __shfl_xor_sync(0xffffffffu, R, 2));
        int cnt = 0, jq = 1 << 20;
        uint32_t qmask = 0;
        #pragma unroll
        for (int nt = 0; nt < 7; ++nt)
            #pragma unroll
            for (int c2 = 0; c2 < 2; ++c2) {
                const int j = nt * 8 + 2 * tig + c2;
                const float dv = d[nt][half * 2 + c2];
                const float m = __fsub_rn(__fadd_rn(sxx, see[j]), 2.0f * dv);
                const float Bv = fmaf(sqxx, sB[j], 3e-4f);
                if (m - Bv <= R) { ++cnt; if (j < jq) jq = j; qmask |= 1u << (nt * 2 + c2); }
            }
        int ct = cnt + __shfl_xor_sync(0xffffffffu, cnt, 1);
        ct += __shfl_xor_sync(0xffffffffu, ct, 2);
        int jt = min(jq, __shfl_xor_sync(0xffffffffu, jq, 1));
        jt = min(jt, __shfl_xor_sync(0xffffffffu, jt, 2));
        if (ct == 1) {
            if (tig == 0) bjsh[row] = jt;             // singleton == exact argmin
        } else {
            if (tig == 0) bjsh[row] = -1;
            uint32_t mrem = qmask;
            while (mrem) {
                const int b = __ffs(mrem) - 1; mrem &= mrem - 1;
                const int j = (b >> 1) * 8 + 2 * tig + (b & 1);
                const uint32_t pos = atomicAdd(qcnt, 1u);
                if (pos < QMAX) queue[pos] = ((uint32_t)row << 8) | (uint32_t)j;
                else atomicOr(&ofl[row >> 5], 1u << (row & 31));
            }
        }
    }
    __syncthreads();

    // ---- rescue: exact chain recompute for multi-candidate rows ----
    const uint32_t qn = min(*qcnt, (uint32_t)QMAX);
    for (uint32_t i = tid; i < qn; i += NTHREADS) {
        const uint32_t ent = queue[i];
        const int row = ent >> 8, j = ent & 255;
        if ((ofl[row >> 5] >> (row & 31)) & 1u) continue;
        int gr = tile_base + row; if (gr >= n) gr = n - 1;
        const float m = exact_m(x4 + (size_t)gr * 48, e4, j, sxx_sh[row], see);
        const unsigned long long key =
            ((unsigned long long)__float_as_uint(m) << 32) | (unsigned long long)j;
        atomicMin(&rkey[row], key);
    }
    for (int r = tid; r < ROWS_PER_BLOCK; r += NTHREADS) {
        if ((ofl[r >> 5] >> (r & 31)) & 1u) {         // overflow: full exact scan
            int gr = tile_base + r; if (gr >= n) gr = n - 1;
            const float4* xr = x4 + (size_t)gr * 48;
            float bv = 3.402823466e38f; int bj = 0;
            for (int j = 0; j < NJ; ++j) {
                const float m = exact_m(xr, e4, j, sxx_sh[r], see);
                if (m < bv) { bv = m; bj = j; }
            }
            bjsh[r] = bj;
        }
    }
    __syncthreads();
    for (int r = tid; r < ROWS_PER_BLOCK; r += NTHREADS) {
        int bj = bjsh[r];
        if (bj < 0) { bj = (int)(rkey[r] & 0xFFull); bjsh[r] = bj; }
        const int grow = tile_base + r;
        if (grow < n) out[(size_t)n * EDIM + grow] = (float)bj;
    }
    __syncthreads();

    // ---- phase 2: coalesced straight-through write + loss ----
    float lsum = 0.f;
    float4* o4 = reinterpret_cast<float4*>(out);
    #pragma unroll 4
    for (int it = 0; it < 24; ++it) {                 // 16 rows * 48 f4 / 32 lanes
        const int idx = it * 32 + lane;
        const int rl = idx / 48, c4 = idx - rl * 48;
        const int row = wid * 16 + rl;
        const int grow = tile_base + row;
        if (grow < n) {
            const int bj = bjsh[row];
            const float4 xq = __ldg(x4 + (size_t)grow * 48 + c4);
            const float4 qq = __ldg(e4 + (size_t)bj * 48 + c4);
            float dx = __fsub_rn(qq.x, xq.x), dy = __fsub_rn(qq.y, xq.y);
            float dz = __fsub_rn(qq.z, xq.z), dw = __fsub_rn(qq.w, xq.w);
            lsum = fmaf(dx, dx, lsum); lsum = fmaf(dy, dy, lsum);
            lsum = fmaf(dz, dz, lsum); lsum = fmaf(dw, dw, lsum);
            float4 o;
            o.x = __fadd_rn(xq.x, dx); o.y = __fadd_rn(xq.y, dy);
            o.z = __fadd_rn(xq.z, dz); o.w = __fadd_rn(xq.w, dw);
            o4[(size_t)grow * 48 + c4] = o;
        }
    }

    // ---- loss reduction + single-kernel finalize ----
    #pragma unroll
    for (int off = 16; off > 0; off >>= 1)
        lsum += __shfl_down_sync(0xffffffffu, lsum, off);
    if (lane == 0) wred[wid] = lsum;
    __syncthreads();
    if (tid == 0) {
        float bs = 0.f;
        #pragma unroll
        for (int w = 0; w < 8; ++w) bs += wred[w];
        atomicAdd(&g_loss_sum, (double)bs);
        __threadfence();
        unsigned int prev = atomicAdd(&g_done, 1u);
        if (prev == gridDim.x - 1) {
            __threadfence();
            double total = atomicAdd(&g_loss_sum, 0.0);
            double mean = total / ((double)n * (double)EDIM);
            out[(size_t)n * EDIM + n]     = (float)(1.25 * mean);  // (1+BETA)*mean
            out[(size_t)n * EDIM + n + 1] = 0.0f;                  // contrastloss
            g_loss_sum = 0.0;
            g_done = 0u;
            __threadfence();
        }
    }
}

extern "C" void kernel_launch(void* const* d_in, const int* in_sizes, int n_in,
                              void* d_out, int out_size) {
    (void)n_in; (void)out_size;
    const float* x = (const float*)d_in[0];   // [N, 192] fp32
    const float* e = (const float*)d_in[1];   // [50, 192] fp32
    float* out = (float*)d_out;               // [N*192 | N | 1 | 1] fp32
    const int n = in_sizes[0] / EDIM;

    static int configured = 0;
    if (!configured) {
        cudaFuncSetAttribute(vq_kernel, cudaFuncAttributeMaxDynamicSharedMemorySize,
                             SMEM_TOTAL);
        configured = 1;
    }
    const int blocks = (n + ROWS_PER_BLOCK - 1) / ROWS_PER_BLOCK;
    vq_kernel<<<blocks, NTHREADS, SMEM_TOTAL>>>(x, e, out, n);
}

// round 13
// speedup vs baseline: 1.3097x; 1.1643x over previous
#include <cuda_runtime.h>
#include <cstdint>

#define NJ 50
#define NJP 56
#define EDIM 192
#define NTHREADS 256
#define ROWS_PER_BLOCK 256
#define QMAX 2048
#define EBS 56            // Eb row stride (u32): Eb[k][j]
#define XSW 36            // xs row stride in floats (32 + 4 pad)

// dynamic smem byte offsets
#define OFF_EB   0                       // 192*56*4 = 43008
#define OFF_XS   43008                   // 256*36*4 = 36864
#define OFF_SXX  79872                   // 256*4
#define OFF_SEE  80896                   // 56*4
#define OFF_SB   81120                   // 56*4
#define OFF_BJ   81344                   // 256*4
#define OFF_RKEY 82368                   // 256*8
#define OFF_Q    84416                   // QMAX*4
#define OFF_QC   92608                   // u32
#define OFF_OFL  92612                   // 8*u32
#define OFF_WRED 92644                   // 8*4
#define SMEM_TOTAL 92704                 // -> 2 CTAs/SM

__device__ double g_loss_sum;    // zero-init at load
__device__ unsigned int g_done;

#define CVT_TF32(u, f) asm("cvt.rna.tf32.f32 %0, %1;" : "=r"(u) : "f"(f))
#define MMA_TF32(d, a0, a1, a2, a3, b0, b1) \
    asm volatile("mma.sync.aligned.m16n8k8.row.col.f32.tf32.tf32.f32 " \
        "{%0,%1,%2,%3}, {%4,%5,%6,%7}, {%8,%9}, {%0,%1,%2,%3};" \
        : "+f"((d)[0]), "+f"((d)[1]), "+f"((d)[2]), "+f"((d)[3]) \
        : "r"(a0), "r"(a1), "r"(a2), "r"(a3), "r"(b0), "r"(b1))

// Exact m for (row x, code j): bit-identical to the R2/R5/R6/R9/R12 passing chain.
static __device__ __forceinline__ float exact_m(const float4* xrow, const float4* e4,
                                                int j, float sxx, const float* see) {
    float dd = 0.f;
    const float4* ej = e4 + (size_t)j * 48;
    #pragma unroll 4
    for (int k0 = 0; k0 < 48; ++k0) {
        const float4 xv = __ldg(xrow + k0);
        const float4 ev = __ldg(ej + k0);
        dd = fmaf(xv.x, ev.x, dd); dd = fmaf(xv.y, ev.y, dd);
        dd = fmaf(xv.z, ev.z, dd); dd = fmaf(xv.w, ev.w, dd);
    }
    return __fsub_rn(__fadd_rn(sxx, see[j]), 2.0f * dd);
}

__global__ void __launch_bounds__(NTHREADS, 2) vq_kernel(
        const float* __restrict__ x, const float* __restrict__ e,
        float* __restrict__ out, int n) {
    extern __shared__ __align__(16) char smem[];
    uint32_t* Eb     = (uint32_t*)(smem + OFF_EB);
    float4*   xs4    = (float4*)(smem + OFF_XS);
    float*    xsf    = (float*)(smem + OFF_XS);
    float*    sxx_sh = (float*)(smem + OFF_SXX);
    float*    see    = (float*)(smem + OFF_SEE);
    float*    sB     = (float*)(smem + OFF_SB);
    int*      bjsh   = (int*)(smem + OFF_BJ);
    unsigned long long* rkey = (unsigned long long*)(smem + OFF_RKEY);
    uint32_t* queue  = (uint32_t*)(smem + OFF_Q);
    uint32_t* qcnt   = (uint32_t*)(smem + OFF_QC);
    uint32_t* ofl    = (uint32_t*)(smem + OFF_OFL);
    float*    wred   = (float*)(smem + OFF_WRED);

    const int tid = threadIdx.x;
    const int wid = tid >> 5;
    const int lane = tid & 31;
    const int gid = lane >> 2;       // 0..7
    const int tig = lane & 3;        // 0..3

    // ---- init ----
    for (int i = tid; i < EDIM * EBS; i += NTHREADS) Eb[i] = 0u;
    if (tid == 0) *qcnt = 0u;
    if (tid < 8) ofl[tid] = 0u;
    rkey[tid] = 0xFFFFFFFFFFFFFFFFull;
    __syncthreads();
    for (int i = tid; i < NJ * EDIM; i += NTHREADS) {
        int j = i / EDIM, k = i - j * EDIM;
        uint32_t u; CVT_TF32(u, __ldg(e + i));
        Eb[k * EBS + j] = u;
    }
    if (tid < NJP) {
        float s = 1e38f;
        if (tid < NJ) {
            s = 0.f;
            const float* ej = e + (size_t)tid * EDIM;
            #pragma unroll 4
            for (int k = 0; k < EDIM; ++k) { float v = __ldg(ej + k); s = fmaf(v, v, s); }
        }
        see[tid] = s;
        sB[tid] = (tid < NJ) ? 2.4e-3f * sqrtf(s) : 0.f;
    }

    const int tile_base = blockIdx.x * ROWS_PER_BLOCK;
    const float4* x4 = reinterpret_cast<const float4*>(x);
    const float4* e4 = reinterpret_cast<const float4*>(e);

    float d2[2][7][4];
    #pragma unroll
    for (int t2 = 0; t2 < 2; ++t2)
        #pragma unroll
        for (int nt = 0; nt < 7; ++nt)
            #pragma unroll
            for (int q = 0; q < 4; ++q) d2[t2][nt][q] = 0.f;
    float s0 = 0.f, s1 = 0.f;        // ||x||^2 partials for row 'tid'

    // ---- main: 6 chunks of 32 k; stage 256 rows coalesced, 2 M-tiles per warp ----
    #pragma unroll 1
    for (int ch = 0; ch < 6; ++ch) {
        __syncthreads();
        #pragma unroll
        for (int i = 0; i < 8; ++i) {                 // 2048 float4 = 256 rows x 8
            const int idx = tid + i * NTHREADS;
            const int row = idx >> 3, kql = idx & 7;
            int gr = tile_base + row; if (gr >= n) gr = n - 1;
            xs4[row * 9 + kql] = __ldg(x4 + (size_t)gr * 48 + ch * 8 + kql);
        }
        __syncthreads();
        {                                             // exact ||x||^2 chain (R2 order)
            #pragma unroll
            for (int q = 0; q < 8; ++q) {
                const float4 v = xs4[tid * 9 + q];
                s0 = fmaf(v.x, v.x, s0); s1 = fmaf(v.y, v.y, s1);
                s0 = fmaf(v.z, v.z, s0); s1 = fmaf(v.w, v.w, s1);
            }
        }
        const int arow = wid * 16 + gid;
        #pragma unroll
        for (int kt = 0; kt < 4; ++kt) {
            const int c = kt * 8 + tig;
            uint32_t a0, a1, a2, a3, a4, a5, a6, a7;
            CVT_TF32(a0, xsf[arow * XSW + c]);
            CVT_TF32(a1, xsf[(arow + 8) * XSW + c]);
            CVT_TF32(a2, xsf[arow * XSW + c + 4]);
            CVT_TF32(a3, xsf[(arow + 8) * XSW + c + 4]);
            CVT_TF32(a4, xsf[(arow + 128) * XSW + c]);
            CVT_TF32(a5, xsf[(arow + 136) * XSW + c]);
            CVT_TF32(a6, xsf[(arow + 128) * XSW + c + 4]);
            CVT_TF32(a7, xsf[(arow + 136) * XSW + c + 4]);
            const int kg = ch * 32 + kt * 8 + tig;
            const uint32_t* eb0 = Eb + (size_t)kg * EBS + gid;
            const uint32_t* eb1 = Eb + (size_t)(kg + 4) * EBS + gid;
            #pragma unroll
            for (int nt = 0; nt < 7; ++nt) {
                const uint32_t b0 = eb0[nt * 8];
                const uint32_t b1 = eb1[nt * 8];
                MMA_TF32(d2[0][nt], a0, a1, a2, a3, b0, b1);
                MMA_TF32(d2[1][nt], a4, a5, a6, a7, b0, b1);
            }
        }
    }
    sxx_sh[tid] = s0 + s1;
    __syncthreads();

    // ---- screen: rigorous candidate set from tf32 dots ----
    #pragma unroll
    for (int t2 = 0; t2 < 2; ++t2)
    #pragma unroll
    for (int half = 0; half < 2; ++half) {
        const int row = t2 * 128 + wid * 16 + gid + half * 8;
        const float sxx = sxx_sh[row];
        const float sqxx = sqrtf(sxx);
        float R = 3.402823466e38f;
        #pragma unroll
        for (int nt = 0; nt < 7; ++nt)
            #pragma unroll
            for (int c2 = 0; c2 < 2; ++c2) {
                const int j = nt * 8 + 2 * tig + c2;
                const float dv = d2[t2][nt][half * 2 + c2];
                const float m = __fsub_rn(__fadd_rn(sxx, see[j]), 2.0f * dv);
                const float Bv = fmaf(sqxx, sB[j], 3e-4f);
                R = fminf(R, m + Bv);
            }
        R = fminf(R, __shfl_xor_sync(0xffffffffu, R, 1));
        R = fminf(R, __shfl_xor_sync(0xffffffffu, R, 2));
        int cnt = 0, jq = 1 << 20;
        uint32_t qmask = 0;
        #pragma unroll
        for (int nt = 0; nt < 7; ++nt)
            #pragma unroll
            for (int c2 = 0; c2 < 2; ++c2) {
                const int j = nt * 8 + 2 * tig + c2;
                const float dv = d2[t2][nt][half * 2 + c2];
                const float m = __fsub_rn(__fadd_rn(sxx, see[j]), 2.0f * dv);
                const float Bv = fmaf(sqxx, sB[j], 3e-4f);
                if (m - Bv <= R) { ++cnt; if (j < jq) jq = j; qmask |= 1u << (nt * 2 + c2); }
            }
        int ct = cnt + __shfl_xor_sync(0xffffffffu, cnt, 1);
        ct += __shfl_xor_sync(0xffffffffu, ct, 2);
        int jt = min(jq, __shfl_xor_sync(0xffffffffu, jq, 1));
        jt = min(jt, __shfl_xor_sync(0xffffffffu, jt, 2));
        if (ct == 1) {
            if (tig == 0) bjsh[row] = jt;             // singleton == exact argmin
        } else {
            if (tig == 0) bjsh[row] = -1;
            uint32_t mrem = qmask;
            while (mrem) {
                const int b = __ffs(mrem) - 1; mrem &= mrem - 1;
                const int j = (b >> 1) * 8 + 2 * tig + (b & 1);
                const uint32_t pos = atomicAdd(qcnt, 1u);
                if (pos < QMAX) queue[pos] = ((uint32_t)row << 8) | (uint32_t)j;
                else atomicOr(&ofl[row >> 5], 1u << (row & 31));
            }
        }
    }
    __syncthreads();

    // ---- rescue: exact chain recompute for multi-candidate rows ----
    const uint32_t qn = min(*qcnt, (uint32_t)QMAX);
    for (uint32_t i = tid; i < qn; i += NTHREADS) {
        const uint32_t ent = queue[i];
        const int row = ent >> 8, j = ent & 255;
        if ((ofl[row >> 5] >> (row & 31)) & 1u) continue;
        int gr = tile_base + row; if (gr >= n) gr = n - 1;
        const float m = exact_m(x4 + (size_t)gr * 48, e4, j, sxx_sh[row], see);
        const unsigned long long key =
            ((unsigned long long)__float_as_uint(m) << 32) | (unsigned long long)j;
        atomicMin(&rkey[row], key);
    }
    {
        const int r = tid;
        if ((ofl[r >> 5] >> (r & 31)) & 1u) {         // overflow: full exact scan
            int gr = tile_base + r; if (gr >= n) gr = n - 1;
            const float4* xr = x4 + (size_t)gr * 48;
            float bv = 3.402823466e38f; int bj = 0;
            for (int j = 0; j < NJ; ++j) {
                const float m = exact_m(xr, e4, j, sxx_sh[r], see);
                if (m < bv) { bv = m; bj = j; }
            }
            bjsh[r] = bj;
        }
    }
    __syncthreads();
    {
        const int r = tid;
        int bj = bjsh[r];
        if (bj < 0) { bj = (int)(rkey[r] & 0xFFull); bjsh[r] = bj; }
        const int grow = tile_base + r;
        if (grow < n) out[(size_t)n * EDIM + grow] = (float)bj;
    }
    __syncthreads();

    // ---- phase 2: coalesced straight-through write + loss ----
    float lsum = 0.f;
    float4* o4 = reinterpret_cast<float4*>(out);
    #pragma unroll 4
    for (int it = 0; it < 48; ++it) {                 // 32 rows * 48 f4 / 32 lanes
        const int idx = it * 32 + lane;
        const int rl = idx / 48, c4 = idx - rl * 48;
        const int row = (rl >> 4) * 128 + wid * 16 + (rl & 15);
        const int grow = tile_base + row;
        if (grow < n) {
            const int bj = bjsh[row];
            const float4 xq = __ldg(x4 + (size_t)grow * 48 + c4);
            const float4 qq = __ldg(e4 + (size_t)bj * 48 + c4);
            float dx = __fsub_rn(qq.x, xq.x), dy = __fsub_rn(qq.y, xq.y);
            float dz = __fsub_rn(qq.z, xq.z), dw = __fsub_rn(qq.w, xq.w);
            lsum = fmaf(dx, dx, lsum); lsum = fmaf(dy, dy, lsum);
            lsum = fmaf(dz, dz, lsum); lsum = fmaf(dw, dw, lsum);
            float4 o;
            o.x = __fadd_rn(xq.x, dx); o.y = __fadd_rn(xq.y, dy);
            o.z = __fadd_rn(xq.z, dz); o.w = __fadd_rn(xq.w, dw);
            o4[(size_t)grow * 48 + c4] = o;
        }
    }

    // ---- loss reduction + single-kernel finalize ----
    #pragma unroll
    for (int off = 16; off > 0; off >>= 1)
        lsum += __shfl_down_sync(0xffffffffu, lsum, off);
    if (lane == 0) wred[wid] = lsum;
    __syncthreads();
    if (tid == 0) {
        float bs = 0.f;
        #pragma unroll
        for (int w = 0; w < 8; ++w) bs += wred[w];
        atomicAdd(&g_loss_sum, (double)bs);
        __threadfence();
        unsigned int prev = atomicAdd(&g_done, 1u);
        if (prev == gridDim.x - 1) {
            __threadfence();
            double total = atomicAdd(&g_loss_sum, 0.0);
            double mean = total / ((double)n * (double)EDIM);
            out[(size_t)n * EDIM + n]     = (float)(1.25 * mean);  // (1+BETA)*mean
            out[(size_t)n * EDIM + n + 1] = 0.0f;                  // contrastloss
            g_loss_sum = 0.0;
            g_done = 0u;
            __threadfence();
        }
    }
}

extern "C" void kernel_launch(void* const* d_in, const int* in_sizes, int n_in,
                              void* d_out, int out_size) {
    (void)n_in; (void)out_size;
    const float* x = (const float*)d_in[0];   // [N, 192] fp32
    const float* e = (const float*)d_in[1];   // [50, 192] fp32
    float* out = (float*)d_out;               // [N*192 | N | 1 | 1] fp32
    const int n = in_sizes[0] / EDIM;

    static int configured = 0;
    if (!configured) {
        cudaFuncSetAttribute(vq_kernel, cudaFuncAttributeMaxDynamicSharedMemorySize,
                             SMEM_TOTAL);
        configured = 1;
    }
    const int blocks = (n + ROWS_PER_BLOCK - 1) / ROWS_PER_BLOCK;
    vq_kernel<<<blocks, NTHREADS, SMEM_TOTAL>>>(x, e, out, n);
}